// round 1
// baseline (speedup 1.0000x reference)
#include <cuda_runtime.h>

// Problem constants (B=2, T=2048, C=1024, H=16, hd=64, MLP width 32)
#define BSZ   2
#define TSEQ  2048
#define CDIM  1024
#define NH    16
#define HD    64
#define MLPW  32

// Scratch: q,k,v each [B][H][T][HD]; y is [B][T][C]
__device__ float g_qkv[3 * BSZ * NH * TSEQ * HD];   // 12.6M floats
__device__ float g_y[BSZ * TSEQ * CDIM];            // 4.2M floats

// ---------------------------------------------------------------------------
// SGEMM 128x128 tile, BK=8, 256 threads, 8x8 per thread.
// MODE 0: qkv = x @ Wqkv + bqkv, scatter into g_qkv ([which][b][h][t][d])
// MODE 1: out = g_y @ Wproj + bproj, plain row-major
// ---------------------------------------------------------------------------
template <int MODE>
__global__ __launch_bounds__(256) void sgemm_kernel(const float* __restrict__ A,
                                                    const float* __restrict__ Bm,
                                                    const float* __restrict__ bias,
                                                    float* __restrict__ out,
                                                    int K, int N) {
    __shared__ float As[8][128];
    __shared__ float Bs[8][128];
    const int tid = threadIdx.x;
    const int tx  = tid & 15;
    const int ty  = tid >> 4;
    const int m0  = blockIdx.y * 128;
    const int n0  = blockIdx.x * 128;

    float acc[8][8];
#pragma unroll
    for (int i = 0; i < 8; i++)
#pragma unroll
        for (int j = 0; j < 8; j++) acc[i][j] = 0.0f;

    const int arow  = tid >> 1;
    const int acol4 = (tid & 1) * 4;
    const int brow  = tid >> 5;
    const int bcol4 = (tid & 31) * 4;

    for (int k0 = 0; k0 < K; k0 += 8) {
        float4 a = *(const float4*)&A[(m0 + arow) * K + k0 + acol4];
        As[acol4 + 0][arow] = a.x;
        As[acol4 + 1][arow] = a.y;
        As[acol4 + 2][arow] = a.z;
        As[acol4 + 3][arow] = a.w;
        *(float4*)&Bs[brow][bcol4] =
            *(const float4*)&Bm[(k0 + brow) * N + n0 + bcol4];
        __syncthreads();
#pragma unroll
        for (int kk = 0; kk < 8; kk++) {
            float af[8], bf[8];
#pragma unroll
            for (int i = 0; i < 8; i++) af[i] = As[kk][ty * 8 + i];
#pragma unroll
            for (int j = 0; j < 8; j++) bf[j] = Bs[kk][tx * 8 + j];
#pragma unroll
            for (int i = 0; i < 8; i++)
#pragma unroll
                for (int j = 0; j < 8; j++)
                    acc[i][j] = fmaf(af[i], bf[j], acc[i][j]);
        }
        __syncthreads();
    }

#pragma unroll
    for (int i = 0; i < 8; i++) {
        const int m = m0 + ty * 8 + i;
#pragma unroll
        for (int j = 0; j < 8; j++) {
            const int n = n0 + tx * 8 + j;
            const float v = acc[i][j] + bias[n];
            if (MODE == 0) {
                // n -> (which, h, d); m -> (b, t)
                const int which = n >> 10;
                const int cc    = n & 1023;
                const int h     = cc >> 6;
                const int d     = cc & 63;
                const int b     = m >> 11;
                const int t     = m & 2047;
                g_qkv[which * (BSZ * NH * TSEQ * HD) +
                      ((b * NH + h) * TSEQ + t) * HD + d] = v;
            } else {
                out[m * N + n] = v;
            }
        }
    }
}

// ---------------------------------------------------------------------------
// Flash attention with fused FIRE bias.
// grid = (T/128, H, B), block = 128 threads. Thread owns one query row:
// q[64] and o[64] register-resident; 32-key K/V tiles staged in smem.
// ---------------------------------------------------------------------------
__global__ __launch_bounds__(128) void attn_kernel(const float* __restrict__ w1,
                                                   const float* __restrict__ b1,
                                                   const float* __restrict__ w2,
                                                   const float* __restrict__ b2,
                                                   const float* __restrict__ cp,
                                                   const float* __restrict__ lm) {
    __shared__ float ks[32 * 64];
    __shared__ float vs[32 * 64];
    __shared__ float sw1[MLPW], sb1[MLPW], sw2[MLPW];

    const int tid = threadIdx.x;
    const int h   = blockIdx.y;
    const int b   = blockIdx.z;
    const int q0  = blockIdx.x * 128;
    const int t   = q0 + tid;

    if (tid < MLPW) {
        sw1[tid] = w1[tid];
        sb1[tid] = b1[tid];
        sw2[tid] = w2[tid * NH + h];   // column h of w2
    }

    const float c   = cp[0];
    const float thr = fabsf(lm[0] * 512.0f);
    const float b2h = b2[h];

    const float* Qg = g_qkv + (b * NH + h) * TSEQ * HD;
    const float* Kg = Qg + BSZ * NH * TSEQ * HD;
    const float* Vg = Kg + BSZ * NH * TSEQ * HD;

    // Load q row, pre-scaled by 1/sqrt(hd)
    float q[HD];
#pragma unroll
    for (int d4 = 0; d4 < 16; d4++) {
        float4 v4 = *(const float4*)&Qg[t * HD + d4 * 4];
        q[d4 * 4 + 0] = v4.x * 0.125f;
        q[d4 * 4 + 1] = v4.y * 0.125f;
        q[d4 * 4 + 2] = v4.z * 0.125f;
        q[d4 * 4 + 3] = v4.w * 0.125f;
    }

    const float invP =
        1.0f / (logf(fabsf(c * fmaxf((float)t, thr)) + 1.0f) + 1e-6f);

    float m = -1e30f, l = 0.0f;
    float o[HD];
#pragma unroll
    for (int d = 0; d < HD; d++) o[d] = 0.0f;

    __syncthreads();  // weights visible

    const int send = q0 + 128;  // exclusive: max key index needed by block
    for (int s0 = 0; s0 < send; s0 += 32) {
        __syncthreads();  // previous tile's consumers done
        {
            const float4* kb  = (const float4*)&Kg[s0 * HD];
            const float4* vb  = (const float4*)&Vg[s0 * HD];
            float4*       ks4 = (float4*)ks;
            float4*       vs4 = (float4*)vs;
#pragma unroll
            for (int i = 0; i < 4; i++) {
                ks4[tid + i * 128] = kb[tid + i * 128];
                vs4[tid + i * 128] = vb[tid + i * 128];
            }
        }
        __syncthreads();

        const int smax = min(32, t - s0 + 1);  // causal: keys s0..min(s0+31,t)
        for (int si = 0; si < smax; si++) {
            const float rel = (float)(t - (s0 + si));
            const float nd  = logf(fabsf(c * rel) + 1.0f) * invP;

            // FIRE bias: b2[h] + sum_w relu(nd*w1[w]+b1[w]) * w2[w][h]
            float sc = b2h;
#pragma unroll
            for (int w = 0; w < MLPW; w++)
                sc = fmaf(fmaxf(fmaf(nd, sw1[w], sb1[w]), 0.0f), sw2[w], sc);

            const float* kr = &ks[si * 64];
#pragma unroll
            for (int d = 0; d < HD; d++) sc = fmaf(q[d], kr[d], sc);

            const float* vr = &vs[si * 64];
            if (sc > m) {
                const float f = __expf(m - sc);
                l = l * f + 1.0f;
#pragma unroll
                for (int d = 0; d < HD; d++) o[d] = fmaf(o[d], f, vr[d]);
                m = sc;
            } else {
                const float p = __expf(sc - m);
                l += p;
#pragma unroll
                for (int d = 0; d < HD; d++) o[d] = fmaf(p, vr[d], o[d]);
            }
        }
    }

    const float inv = 1.0f / l;
    float* yrow = &g_y[(b * TSEQ + t) * CDIM + h * HD];
#pragma unroll
    for (int d4 = 0; d4 < 16; d4++) {
        float4 v4 = make_float4(o[d4 * 4 + 0] * inv, o[d4 * 4 + 1] * inv,
                                o[d4 * 4 + 2] * inv, o[d4 * 4 + 3] * inv);
        *(float4*)&yrow[d4 * 4] = v4;
    }
}

// ---------------------------------------------------------------------------
// Inputs (metadata order): x, Wqkv, bqkv, Wproj, bproj, w1, b1, w2, b2,
//                          c_param, L_multiplier. Output: (B,T,C) float32.
// ---------------------------------------------------------------------------
extern "C" void kernel_launch(void* const* d_in, const int* in_sizes, int n_in,
                              void* d_out, int out_size) {
    const float* x     = (const float*)d_in[0];
    const float* Wqkv  = (const float*)d_in[1];
    const float* bqkv  = (const float*)d_in[2];
    const float* Wproj = (const float*)d_in[3];
    const float* bproj = (const float*)d_in[4];
    const float* w1    = (const float*)d_in[5];
    const float* b1    = (const float*)d_in[6];
    const float* w2    = (const float*)d_in[7];
    const float* b2    = (const float*)d_in[8];
    const float* cpar  = (const float*)d_in[9];
    const float* lmul  = (const float*)d_in[10];
    float* out = (float*)d_out;

    // 1) QKV GEMM: (4096 x 1024) @ (1024 x 3072), scatter to [B,H,T,hd]
    sgemm_kernel<0><<<dim3(3 * CDIM / 128, BSZ * TSEQ / 128), 256>>>(
        x, Wqkv, bqkv, nullptr, CDIM, 3 * CDIM);

    // 2) Flash attention + fused FIRE bias
    attn_kernel<<<dim3(TSEQ / 128, NH, BSZ), 128>>>(w1, b1, w2, b2, cpar, lmul);

    // 3) Projection GEMM: (4096 x 1024) @ (1024 x 1024) -> out
    float* gy_ptr = nullptr;
    cudaGetSymbolAddress((void**)&gy_ptr, g_y);
    sgemm_kernel<1><<<dim3(CDIM / 128, BSZ * TSEQ / 128), 256>>>(
        gy_ptr, Wproj, bproj, out, CDIM, CDIM);
}

// round 2
// speedup vs baseline: 1.4024x; 1.4024x over previous
#include <cuda_runtime.h>

// Problem constants (B=2, T=2048, C=1024, H=16, hd=64, MLP width 32)
#define BSZ   2
#define TSEQ  2048
#define CDIM  1024
#define NH    16
#define HD    64
#define MLPW  32

// Scratch: q,k,v each [B][H][T][HD]; y is [B][T][C]
__device__ float g_qkv[3 * BSZ * NH * TSEQ * HD];
__device__ float g_y[BSZ * TSEQ * CDIM];
__device__ float g_utab[TSEQ];   // log(|c*rel|+1)
__device__ float g_invP[TSEQ];   // 1/(log(|c*max(t,thr)|+1)+eps)

// ---------------------------------------------------------------------------
// Init: FIRE log tables (shared across all b,h — removes logf from hot loop)
// ---------------------------------------------------------------------------
__global__ void init_tables(const float* __restrict__ cp,
                            const float* __restrict__ lm) {
    const int i = blockIdx.x * blockDim.x + threadIdx.x;
    if (i >= TSEQ) return;
    const float c   = cp[0];
    const float thr = fabsf(lm[0] * 512.0f);
    g_utab[i] = logf(fabsf(c * (float)i) + 1.0f);
    g_invP[i] = 1.0f / (logf(fabsf(c * fmaxf((float)i, thr)) + 1.0f) + 1e-6f);
}

// ---------------------------------------------------------------------------
// SGEMM 128x128 tile, BK=16, 256 threads, 8x8/thread, double-buffered smem.
// MODE 0: qkv = x @ Wqkv + bqkv, scatter into g_qkv ([which][b][h][t][d])
// MODE 1: out = g_y @ Wproj + bproj, plain row-major
// ---------------------------------------------------------------------------
template <int MODE>
__global__ __launch_bounds__(256) void sgemm_kernel(const float* __restrict__ A,
                                                    const float* __restrict__ Bm,
                                                    const float* __restrict__ bias,
                                                    float* __restrict__ out,
                                                    int K, int N) {
    __shared__ float As[2][16][128];
    __shared__ float Bs[2][16][128];
    const int tid = threadIdx.x;
    const int tx  = tid & 15;
    const int ty  = tid >> 4;
    const int m0  = blockIdx.y * 128;
    const int n0  = blockIdx.x * 128;

    // A loader: row = tid>>1 (0..127), two float4 at k-cols (tid&1)*8, +4
    const int arow = tid >> 1;
    const int ac   = (tid & 1) * 8;
    // B loader: row = tid>>4 (0..15), two float4 at cols (tid&15)*8, +4
    const int brow = tid >> 4;
    const int bc   = (tid & 15) * 8;

    const float* Ap = A + (m0 + arow) * K + ac;
    const float* Bp = Bm + brow * N + n0 + bc;

    float4 a0, a1, b0, b1;
    a0 = *(const float4*)(Ap);
    a1 = *(const float4*)(Ap + 4);
    b0 = *(const float4*)(Bp);
    b1 = *(const float4*)(Bp + 4);

    As[0][ac + 0][arow] = a0.x; As[0][ac + 1][arow] = a0.y;
    As[0][ac + 2][arow] = a0.z; As[0][ac + 3][arow] = a0.w;
    As[0][ac + 4][arow] = a1.x; As[0][ac + 5][arow] = a1.y;
    As[0][ac + 6][arow] = a1.z; As[0][ac + 7][arow] = a1.w;
    *(float4*)&Bs[0][brow][bc]     = b0;
    *(float4*)&Bs[0][brow][bc + 4] = b1;
    __syncthreads();

    float acc[8][8];
#pragma unroll
    for (int i = 0; i < 8; i++)
#pragma unroll
        for (int j = 0; j < 8; j++) acc[i][j] = 0.0f;

    const int nk = K >> 4;
    int buf = 0;
    for (int kt = 0; kt < nk; kt++) {
        if (kt + 1 < nk) {
            const float* Apn = Ap + (kt + 1) * 16;
            const float* Bpn = Bp + (kt + 1) * 16 * N;
            a0 = *(const float4*)(Apn);
            a1 = *(const float4*)(Apn + 4);
            b0 = *(const float4*)(Bpn);
            b1 = *(const float4*)(Bpn + 4);
        }
#pragma unroll
        for (int kk = 0; kk < 16; kk++) {
            float af[8], bf[8];
            *(float4*)&af[0] = *(const float4*)&As[buf][kk][ty * 8];
            *(float4*)&af[4] = *(const float4*)&As[buf][kk][ty * 8 + 4];
            *(float4*)&bf[0] = *(const float4*)&Bs[buf][kk][tx * 8];
            *(float4*)&bf[4] = *(const float4*)&Bs[buf][kk][tx * 8 + 4];
#pragma unroll
            for (int i = 0; i < 8; i++)
#pragma unroll
                for (int j = 0; j < 8; j++)
                    acc[i][j] = fmaf(af[i], bf[j], acc[i][j]);
        }
        if (kt + 1 < nk) {
            const int nb = buf ^ 1;
            As[nb][ac + 0][arow] = a0.x; As[nb][ac + 1][arow] = a0.y;
            As[nb][ac + 2][arow] = a0.z; As[nb][ac + 3][arow] = a0.w;
            As[nb][ac + 4][arow] = a1.x; As[nb][ac + 5][arow] = a1.y;
            As[nb][ac + 6][arow] = a1.z; As[nb][ac + 7][arow] = a1.w;
            *(float4*)&Bs[nb][brow][bc]     = b0;
            *(float4*)&Bs[nb][brow][bc + 4] = b1;
            __syncthreads();
            buf = nb;
        }
    }

#pragma unroll
    for (int i = 0; i < 8; i++) {
        const int m = m0 + ty * 8 + i;
#pragma unroll
        for (int j = 0; j < 8; j++) {
            const int n = n0 + tx * 8 + j;
            const float v = acc[i][j] + bias[n];
            if (MODE == 0) {
                const int which = n >> 10;
                const int cc    = n & 1023;
                const int h     = cc >> 6;
                const int d     = cc & 63;
                const int b     = m >> 11;
                const int t     = m & 2047;
                g_qkv[which * (BSZ * NH * TSEQ * HD) +
                      ((b * NH + h) * TSEQ + t) * HD + d] = v;
            } else {
                out[m * N + n] = v;
            }
        }
    }
}

// ---------------------------------------------------------------------------
// Flash attention with fused FIRE bias (branchless two-phase tiles).
// grid = (T/128, H, B), block = 128 threads, thread owns one query row.
// FIRE fast path: if b1 == 0 (true for this problem's inputs) and nd >= 0,
// the ReLU MLP is exactly linear: bias = nd * alpha_h + b2_h.
// ---------------------------------------------------------------------------
__global__ __launch_bounds__(128, 2) void attn_kernel(
        const float* __restrict__ w1, const float* __restrict__ b1,
        const float* __restrict__ w2, const float* __restrict__ b2) {
    __shared__ float ks[32 * 64];
    __shared__ float vs[32 * 64];
    __shared__ float scs[128 * 33];          // padded: bank-conflict free
    __shared__ float sw1[MLPW], sb1[MLPW], sw2[MLPW];
    __shared__ float s_alpha;
    __shared__ int   s_linear;

    const int tid = threadIdx.x;
    const int h   = blockIdx.y;
    const int b   = blockIdx.z;
    const int q0  = (gridDim.x - 1 - blockIdx.x) * 128;  // heavy blocks first
    const int t   = q0 + tid;

    if (tid < MLPW) {
        sw1[tid] = w1[tid];
        sb1[tid] = b1[tid];
        sw2[tid] = w2[tid * NH + h];
    }
    __syncthreads();
    if (tid == 0) {
        bool  lin = true;
        float a   = 0.0f;
#pragma unroll
        for (int w = 0; w < MLPW; w++) {
            lin = lin && (sb1[w] == 0.0f);
            a   = fmaf(fmaxf(sw1[w], 0.0f), sw2[w], a);
        }
        s_alpha  = a;
        s_linear = lin ? 1 : 0;
    }

    const float b2h  = b2[h];
    const float invP = g_invP[t];

    const float* Qg = g_qkv + (b * NH + h) * TSEQ * HD;
    const float* Kg = Qg + BSZ * NH * TSEQ * HD;
    const float* Vg = Kg + BSZ * NH * TSEQ * HD;

    float q[HD];
#pragma unroll
    for (int d4 = 0; d4 < 16; d4++) {
        float4 v4 = *(const float4*)&Qg[t * HD + d4 * 4];
        q[d4 * 4 + 0] = v4.x * 0.125f;
        q[d4 * 4 + 1] = v4.y * 0.125f;
        q[d4 * 4 + 2] = v4.z * 0.125f;
        q[d4 * 4 + 3] = v4.w * 0.125f;
    }

    float m = -1e30f, l = 0.0f;
    float o[HD];
#pragma unroll
    for (int d = 0; d < HD; d++) o[d] = 0.0f;

    __syncthreads();
    const int   linear = s_linear;
    const float alpha  = s_alpha;

    const int nt = (q0 + 128) >> 5;
    for (int it = 0; it < nt; it++) {
        const int s0 = it * 32;
        __syncthreads();  // prior tile consumers done
        {
            const float4* kb  = (const float4*)&Kg[s0 * HD];
            const float4* vb  = (const float4*)&Vg[s0 * HD];
            float4*       ks4 = (float4*)ks;
            float4*       vs4 = (float4*)vs;
#pragma unroll
            for (int i = 0; i < 4; i++) {
                ks4[tid + i * 128] = kb[tid + i * 128];
                vs4[tid + i * 128] = vb[tid + i * 128];
            }
        }
        __syncthreads();

        // ---- phase 1: scores -> smem, track tile max (branchless mask) ----
        float mt = -1e30f;
#pragma unroll 4
        for (int si = 0; si < 32; si++) {
            const int   rel  = t - (s0 + si);
            const int   relc = rel < 0 ? 0 : rel;
            const float nd   = g_utab[relc] * invP;
            float sc;
            if (linear) {
                sc = fmaf(nd, alpha, b2h);
            } else {
                sc = b2h;
#pragma unroll
                for (int w = 0; w < MLPW; w++)
                    sc = fmaf(fmaxf(fmaf(nd, sw1[w], sb1[w]), 0.0f), sw2[w], sc);
            }
            const float4* kr = (const float4*)&ks[si * 64];
#pragma unroll
            for (int d4 = 0; d4 < 16; d4++) {
                float4 kv = kr[d4];
                sc = fmaf(q[d4 * 4 + 0], kv.x, sc);
                sc = fmaf(q[d4 * 4 + 1], kv.y, sc);
                sc = fmaf(q[d4 * 4 + 2], kv.z, sc);
                sc = fmaf(q[d4 * 4 + 3], kv.w, sc);
            }
            sc = (rel >= 0) ? sc : -1e30f;
            scs[tid * 33 + si] = sc;
            mt = fmaxf(mt, sc);
        }

        // ---- single rescale per tile ----
        const float mnew = fmaxf(m, mt);
        const float f    = __expf(m - mnew);
        m = mnew;
        l *= f;
#pragma unroll
        for (int d = 0; d < HD; d++) o[d] *= f;

        // ---- phase 2: exp + PV accumulate ----
#pragma unroll 4
        for (int si = 0; si < 32; si++) {
            const float p = __expf(scs[tid * 33 + si] - m);
            l += p;
            const float4* vr = (const float4*)&vs[si * 64];
#pragma unroll
            for (int d4 = 0; d4 < 16; d4++) {
                float4 vv = vr[d4];
                o[d4 * 4 + 0] = fmaf(p, vv.x, o[d4 * 4 + 0]);
                o[d4 * 4 + 1] = fmaf(p, vv.y, o[d4 * 4 + 1]);
                o[d4 * 4 + 2] = fmaf(p, vv.z, o[d4 * 4 + 2]);
                o[d4 * 4 + 3] = fmaf(p, vv.w, o[d4 * 4 + 3]);
            }
        }
    }

    const float inv = 1.0f / l;
    float* yrow = &g_y[(b * TSEQ + t) * CDIM + h * HD];
#pragma unroll
    for (int d4 = 0; d4 < 16; d4++) {
        *(float4*)&yrow[d4 * 4] =
            make_float4(o[d4 * 4 + 0] * inv, o[d4 * 4 + 1] * inv,
                        o[d4 * 4 + 2] * inv, o[d4 * 4 + 3] * inv);
    }
}

// ---------------------------------------------------------------------------
// Inputs (metadata order): x, Wqkv, bqkv, Wproj, bproj, w1, b1, w2, b2,
//                          c_param, L_multiplier. Output: (B,T,C) float32.
// ---------------------------------------------------------------------------
extern "C" void kernel_launch(void* const* d_in, const int* in_sizes, int n_in,
                              void* d_out, int out_size) {
    const float* x     = (const float*)d_in[0];
    const float* Wqkv  = (const float*)d_in[1];
    const float* bqkv  = (const float*)d_in[2];
    const float* Wproj = (const float*)d_in[3];
    const float* bproj = (const float*)d_in[4];
    const float* w1    = (const float*)d_in[5];
    const float* b1    = (const float*)d_in[6];
    const float* w2    = (const float*)d_in[7];
    const float* b2    = (const float*)d_in[8];
    const float* cpar  = (const float*)d_in[9];
    const float* lmul  = (const float*)d_in[10];
    float* out = (float*)d_out;

    init_tables<<<TSEQ / 256, 256>>>(cpar, lmul);

    sgemm_kernel<0><<<dim3(3 * CDIM / 128, BSZ * TSEQ / 128), 256>>>(
        x, Wqkv, bqkv, nullptr, CDIM, 3 * CDIM);

    attn_kernel<<<dim3(TSEQ / 128, NH, BSZ), 128>>>(w1, b1, w2, b2);

    float* gy_ptr = nullptr;
    cudaGetSymbolAddress((void**)&gy_ptr, g_y);
    sgemm_kernel<1><<<dim3(CDIM / 128, BSZ * TSEQ / 128), 256>>>(
        gy_ptr, Wproj, bproj, out, CDIM, CDIM);
}

// round 4
// speedup vs baseline: 2.1664x; 1.5448x over previous
#include <cuda_runtime.h>
#include <cstdint>

// Problem constants (B=2, T=2048, C=1024, H=16, hd=64, MLP width 32)
#define BSZ   2
#define TSEQ  2048
#define CDIM  1024
#define NH    16
#define HD    64
#define MLPW  32

__device__ float g_qkv[3 * BSZ * NH * TSEQ * HD];
__device__ float g_y[BSZ * TSEQ * CDIM];
__device__ float g_utab[TSEQ];   // log(|c*rel|+1)
__device__ float g_invP[TSEQ];   // 1/(log(|c*max(t,thr)|+1)+eps)

// ===========================================================================
// Helpers: cp.async (sm_80 baseline), tf32 convert, mma.sync m16n8k8
// ===========================================================================
__device__ __forceinline__ uint32_t smem_u32(const void* p) {
    uint32_t a;
    asm("{ .reg .u64 t; cvta.to.shared.u64 t, %1; cvt.u32.u64 %0, t; }"
        : "=r"(a) : "l"(p));
    return a;
}
#define CP_ASYNC16(dst, src) \
    asm volatile("cp.async.cg.shared.global [%0], [%1], 16;" \
                 :: "r"(dst), "l"(src) : "memory")
#define CP_COMMIT() asm volatile("cp.async.commit_group;" ::: "memory")
#define CP_WAIT(n)  asm volatile("cp.async.wait_group %0;" :: "n"(n) : "memory")

__device__ __forceinline__ uint32_t f2tf32(float f) {
    uint32_t r;
    asm("cvt.rna.tf32.f32 %0, %1;" : "=r"(r) : "f"(f));
    return r;
}
__device__ __forceinline__ void mma8(float* c, const uint32_t* a,
                                     const uint32_t* b) {
    asm volatile(
        "mma.sync.aligned.m16n8k8.row.col.f32.tf32.tf32.f32 "
        "{%0,%1,%2,%3}, {%4,%5,%6,%7}, {%8,%9}, {%0,%1,%2,%3};"
        : "+f"(c[0]), "+f"(c[1]), "+f"(c[2]), "+f"(c[3])
        : "r"(a[0]), "r"(a[1]), "r"(a[2]), "r"(a[3]), "r"(b[0]), "r"(b[1]));
}

// ===========================================================================
// Init: FIRE log tables
// ===========================================================================
__global__ void init_tables(const float* __restrict__ cp,
                            const float* __restrict__ lm) {
    const int i = blockIdx.x * blockDim.x + threadIdx.x;
    if (i >= TSEQ) return;
    const float c   = cp[0];
    const float thr = fabsf(lm[0] * 512.0f);
    g_utab[i] = logf(fabsf(c * (float)i) + 1.0f);
    g_invP[i] = 1.0f / (logf(fabsf(c * fmaxf((float)i, thr)) + 1.0f) + 1e-6f);
}

// ===========================================================================
// tf32 mma.sync GEMM: C[M,N] = A[M,K] @ B[K,N] + bias.
// 128x128 CTA tile, BK=16, 256 thr / 8 warps (4x2), warp tile 32x64.
// cp.async double-buffered smem. MODE 0: scatter to g_qkv; MODE 1: row-major.
// ===========================================================================
template <int MODE>
__global__ __launch_bounds__(256) void mma_gemm(const float* __restrict__ A,
                                                const float* __restrict__ Bm,
                                                const float* __restrict__ bias,
                                                float* __restrict__ out,
                                                int K, int N) {
    __shared__ float As[2][128][20];   // [m][k], pitch 20 -> conflict-free frags
    __shared__ float Bs[2][16][136];   // [k][n], pitch 136 -> conflict-free frags

    const int tid   = threadIdx.x;
    const int lane  = tid & 31;
    const int wid   = tid >> 5;
    const int warpM = wid & 3;        // 4 warps over M
    const int warpN = wid >> 2;       // 2 warps over N
    const int m0    = blockIdx.y * 128;
    const int n0    = blockIdx.x * 128;

    // A loader: rows tid>>2 and (tid>>2)+64, k-vec (tid&3)*4
    const int ar = tid >> 2;
    const int ak = (tid & 3) * 4;
    const float* Ag = A + (size_t)(m0 + ar) * K + ak;
    // B loader: row tid>>4, col vecs (tid&15)*4 and +64
    const int br = tid >> 4;
    const int bc = (tid & 15) * 4;
    const float* Bg = Bm + (size_t)br * N + n0 + bc;

    const uint32_t sA = smem_u32(As);
    const uint32_t sB = smem_u32(Bs);
    const uint32_t aOff0 = (uint32_t)(ar * 20 + ak) * 4;
    const uint32_t aOff1 = (uint32_t)((ar + 64) * 20 + ak) * 4;
    const uint32_t bOff0 = (uint32_t)(br * 136 + bc) * 4;
    const uint32_t bOff1 = (uint32_t)(br * 136 + bc + 64) * 4;
    const uint32_t ABUF = 128 * 20 * 4;
    const uint32_t BBUF = 16 * 136 * 4;

#define LOADTILE(buf, kc)                                                  \
    do {                                                                   \
        CP_ASYNC16(sA + (buf) * ABUF + aOff0, Ag + (kc));                  \
        CP_ASYNC16(sA + (buf) * ABUF + aOff1, Ag + (size_t)64 * K + (kc)); \
        CP_ASYNC16(sB + (buf) * BBUF + bOff0, Bg + (size_t)(kc) * N);      \
        CP_ASYNC16(sB + (buf) * BBUF + bOff1, Bg + (size_t)(kc) * N + 64); \
        CP_COMMIT();                                                       \
    } while (0)

    float acc[2][8][4];
#pragma unroll
    for (int mf = 0; mf < 2; mf++)
#pragma unroll
        for (int nf = 0; nf < 8; nf++)
#pragma unroll
            for (int i = 0; i < 4; i++) acc[mf][nf][i] = 0.0f;

    const int r  = lane >> 2;   // A row / B col within frag
    const int cq = lane & 3;    // A col / B row within frag
    const int nk = K >> 4;

    LOADTILE(0, 0);

#pragma unroll 1
    for (int it = 0; it < nk; it++) {
        const int buf = it & 1;
        if (it + 1 < nk) {
            LOADTILE((it + 1) & 1, (it + 1) * 16);
            CP_WAIT(1);
        } else {
            CP_WAIT(0);
        }
        __syncthreads();

#pragma unroll
        for (int ks = 0; ks < 2; ks++) {
            const int kb = ks * 8;
            uint32_t af[2][4];
#pragma unroll
            for (int mf = 0; mf < 2; mf++) {
                const int mrow = warpM * 32 + mf * 16 + r;
                af[mf][0] = f2tf32(As[buf][mrow][kb + cq]);
                af[mf][1] = f2tf32(As[buf][mrow + 8][kb + cq]);
                af[mf][2] = f2tf32(As[buf][mrow][kb + cq + 4]);
                af[mf][3] = f2tf32(As[buf][mrow + 8][kb + cq + 4]);
            }
#pragma unroll
            for (int nf = 0; nf < 8; nf++) {
                const int ncol = warpN * 64 + nf * 8 + r;
                uint32_t bf[2];
                bf[0] = f2tf32(Bs[buf][kb + cq][ncol]);
                bf[1] = f2tf32(Bs[buf][kb + cq + 4][ncol]);
                mma8(acc[0][nf], af[0], bf);
                mma8(acc[1][nf], af[1], bf);
            }
        }
        __syncthreads();
    }

    // Epilogue: c0,c1 at (row, 2c), (row, 2c+1); c2,c3 at (row+8, ...)
#pragma unroll
    for (int mf = 0; mf < 2; mf++) {
#pragma unroll
        for (int nf = 0; nf < 8; nf++) {
            const int n = n0 + warpN * 64 + nf * 8 + 2 * cq;
            const float bx = bias[n], by = bias[n + 1];
#pragma unroll
            for (int half = 0; half < 2; half++) {
                const int m = m0 + warpM * 32 + mf * 16 + r + half * 8;
                float2 v = make_float2(acc[mf][nf][half * 2] + bx,
                                       acc[mf][nf][half * 2 + 1] + by);
                if (MODE == 0) {
                    const int which = n >> 10;
                    const int h     = (n & 1023) >> 6;
                    const int d     = n & 63;
                    const int b     = m >> 11;
                    const int t     = m & 2047;
                    *(float2*)&g_qkv[which * (BSZ * NH * TSEQ * HD) +
                                     ((b * NH + h) * TSEQ + t) * HD + d] = v;
                } else {
                    *(float2*)&out[(size_t)m * N + n] = v;
                }
            }
        }
    }
#undef LOADTILE
}

// ===========================================================================
// Flash attention with fused FIRE bias (unchanged from R2 — fp32).
// ===========================================================================
__global__ __launch_bounds__(128, 2) void attn_kernel(
        const float* __restrict__ w1, const float* __restrict__ b1,
        const float* __restrict__ w2, const float* __restrict__ b2) {
    __shared__ float ks[32 * 64];
    __shared__ float vs[32 * 64];
    __shared__ float scs[128 * 33];
    __shared__ float sw1[MLPW], sb1[MLPW], sw2[MLPW];
    __shared__ float s_alpha;
    __shared__ int   s_linear;

    const int tid = threadIdx.x;
    const int h   = blockIdx.y;
    const int b   = blockIdx.z;
    const int q0  = (gridDim.x - 1 - blockIdx.x) * 128;
    const int t   = q0 + tid;

    if (tid < MLPW) {
        sw1[tid] = w1[tid];
        sb1[tid] = b1[tid];
        sw2[tid] = w2[tid * NH + h];
    }
    __syncthreads();
    if (tid == 0) {
        bool  lin = true;
        float a   = 0.0f;
#pragma unroll
        for (int w = 0; w < MLPW; w++) {
            lin = lin && (sb1[w] == 0.0f);
            a   = fmaf(fmaxf(sw1[w], 0.0f), sw2[w], a);
        }
        s_alpha  = a;
        s_linear = lin ? 1 : 0;
    }

    const float b2h  = b2[h];
    const float invP = g_invP[t];

    const float* Qg = g_qkv + (b * NH + h) * TSEQ * HD;
    const float* Kg = Qg + BSZ * NH * TSEQ * HD;
    const float* Vg = Kg + BSZ * NH * TSEQ * HD;

    float q[HD];
#pragma unroll
    for (int d4 = 0; d4 < 16; d4++) {
        float4 v4 = *(const float4*)&Qg[t * HD + d4 * 4];
        q[d4 * 4 + 0] = v4.x * 0.125f;
        q[d4 * 4 + 1] = v4.y * 0.125f;
        q[d4 * 4 + 2] = v4.z * 0.125f;
        q[d4 * 4 + 3] = v4.w * 0.125f;
    }

    float m = -1e30f, l = 0.0f;
    float o[HD];
#pragma unroll
    for (int d = 0; d < HD; d++) o[d] = 0.0f;

    __syncthreads();
    const int   linear = s_linear;
    const float alpha  = s_alpha;

    const int nt = (q0 + 128) >> 5;
    for (int it = 0; it < nt; it++) {
        const int s0 = it * 32;
        __syncthreads();
        {
            const float4* kb  = (const float4*)&Kg[s0 * HD];
            const float4* vb  = (const float4*)&Vg[s0 * HD];
            float4*       ks4 = (float4*)ks;
            float4*       vs4 = (float4*)vs;
#pragma unroll
            for (int i = 0; i < 4; i++) {
                ks4[tid + i * 128] = kb[tid + i * 128];
                vs4[tid + i * 128] = vb[tid + i * 128];
            }
        }
        __syncthreads();

        float mt = -1e30f;
#pragma unroll 4
        for (int si = 0; si < 32; si++) {
            const int   rel  = t - (s0 + si);
            const int   relc = rel < 0 ? 0 : rel;
            const float nd   = g_utab[relc] * invP;
            float sc;
            if (linear) {
                sc = fmaf(nd, alpha, b2h);
            } else {
                sc = b2h;
#pragma unroll
                for (int w = 0; w < MLPW; w++)
                    sc = fmaf(fmaxf(fmaf(nd, sw1[w], sb1[w]), 0.0f), sw2[w], sc);
            }
            const float4* kr = (const float4*)&ks[si * 64];
#pragma unroll
            for (int d4 = 0; d4 < 16; d4++) {
                float4 kv = kr[d4];
                sc = fmaf(q[d4 * 4 + 0], kv.x, sc);
                sc = fmaf(q[d4 * 4 + 1], kv.y, sc);
                sc = fmaf(q[d4 * 4 + 2], kv.z, sc);
                sc = fmaf(q[d4 * 4 + 3], kv.w, sc);
            }
            sc = (rel >= 0) ? sc : -1e30f;
            scs[tid * 33 + si] = sc;
            mt = fmaxf(mt, sc);
        }

        const float mnew = fmaxf(m, mt);
        const float f    = __expf(m - mnew);
        m = mnew;
        l *= f;
#pragma unroll
        for (int d = 0; d < HD; d++) o[d] *= f;

#pragma unroll 4
        for (int si = 0; si < 32; si++) {
            const float p = __expf(scs[tid * 33 + si] - m);
            l += p;
            const float4* vr = (const float4*)&vs[si * 64];
#pragma unroll
            for (int d4 = 0; d4 < 16; d4++) {
                float4 vv = vr[d4];
                o[d4 * 4 + 0] = fmaf(p, vv.x, o[d4 * 4 + 0]);
                o[d4 * 4 + 1] = fmaf(p, vv.y, o[d4 * 4 + 1]);
                o[d4 * 4 + 2] = fmaf(p, vv.z, o[d4 * 4 + 2]);
                o[d4 * 4 + 3] = fmaf(p, vv.w, o[d4 * 4 + 3]);
            }
        }
    }

    const float inv = 1.0f / l;
    float* yrow = &g_y[(b * TSEQ + t) * CDIM + h * HD];
#pragma unroll
    for (int d4 = 0; d4 < 16; d4++) {
        *(float4*)&yrow[d4 * 4] =
            make_float4(o[d4 * 4 + 0] * inv, o[d4 * 4 + 1] * inv,
                        o[d4 * 4 + 2] * inv, o[d4 * 4 + 3] * inv);
    }
}

// ===========================================================================
// Launch
// ===========================================================================
extern "C" void kernel_launch(void* const* d_in, const int* in_sizes, int n_in,
                              void* d_out, int out_size) {
    const float* x     = (const float*)d_in[0];
    const float* Wqkv  = (const float*)d_in[1];
    const float* bqkv  = (const float*)d_in[2];
    const float* Wproj = (const float*)d_in[3];
    const float* bproj = (const float*)d_in[4];
    const float* w1    = (const float*)d_in[5];
    const float* b1    = (const float*)d_in[6];
    const float* w2    = (const float*)d_in[7];
    const float* b2    = (const float*)d_in[8];
    const float* cpar  = (const float*)d_in[9];
    const float* lmul  = (const float*)d_in[10];
    float* out = (float*)d_out;

    init_tables<<<TSEQ / 256, 256>>>(cpar, lmul);

    // QKV: (4096 x 1024) @ (1024 x 3072) -> scatter into g_qkv
    mma_gemm<0><<<dim3(3 * CDIM / 128, BSZ * TSEQ / 128), 256>>>(
        x, Wqkv, bqkv, nullptr, CDIM, 3 * CDIM);

    attn_kernel<<<dim3(TSEQ / 128, NH, BSZ), 128>>>(w1, b1, w2, b2);

    // Proj: (4096 x 1024) @ (1024 x 1024) -> out
    float* gy_ptr = nullptr;
    cudaGetSymbolAddress((void**)&gy_ptr, g_y);
    mma_gemm<1><<<dim3(CDIM / 128, BSZ * TSEQ / 128), 256>>>(
        gy_ptr, Wproj, bproj, out, CDIM, CDIM);
}

// round 5
// speedup vs baseline: 4.5060x; 2.0799x over previous
#include <cuda_runtime.h>
#include <cstdint>

// Problem constants (B=2, T=2048, C=1024, H=16, hd=64, MLP width 32)
#define BSZ   2
#define TSEQ  2048
#define CDIM  1024
#define NH    16
#define HD    64
#define MLPW  32

__device__ float g_qkv[3 * BSZ * NH * TSEQ * HD];
__device__ float g_y[BSZ * TSEQ * CDIM];
__device__ float g_utab[TSEQ];   // log(|c*rel|+1)
__device__ float g_invP[TSEQ];   // 1/(log(|c*max(t,thr)|+1)+eps)

// ===========================================================================
// Helpers
// ===========================================================================
__device__ __forceinline__ uint32_t smem_u32(const void* p) {
    uint32_t a;
    asm("{ .reg .u64 t; cvta.to.shared.u64 t, %1; cvt.u32.u64 %0, t; }"
        : "=r"(a) : "l"(p));
    return a;
}
#define CP_ASYNC16(dst, src) \
    asm volatile("cp.async.cg.shared.global [%0], [%1], 16;" \
                 :: "r"(dst), "l"(src) : "memory")
#define CP_COMMIT() asm volatile("cp.async.commit_group;" ::: "memory")
#define CP_WAIT(n)  asm volatile("cp.async.wait_group %0;" :: "n"(n) : "memory")

__device__ __forceinline__ uint32_t f2tf32(float f) {
    uint32_t r;
    asm("cvt.rna.tf32.f32 %0, %1;" : "=r"(r) : "f"(f));
    return r;
}
__device__ __forceinline__ float rnaf(float f) {
    return __uint_as_float(f2tf32(f));
}
__device__ __forceinline__ void mma8(float* c, const uint32_t* a,
                                     const uint32_t* b) {
    asm volatile(
        "mma.sync.aligned.m16n8k8.row.col.f32.tf32.tf32.f32 "
        "{%0,%1,%2,%3}, {%4,%5,%6,%7}, {%8,%9}, {%0,%1,%2,%3};"
        : "+f"(c[0]), "+f"(c[1]), "+f"(c[2]), "+f"(c[3])
        : "r"(a[0]), "r"(a[1]), "r"(a[2]), "r"(a[3]), "r"(b[0]), "r"(b[1]));
}
__device__ __forceinline__ void ldm_x4(uint32_t& r0, uint32_t& r1,
                                       uint32_t& r2, uint32_t& r3,
                                       uint32_t addr) {
    asm volatile(
        "ldmatrix.sync.aligned.m8n8.x4.shared.b16 {%0,%1,%2,%3}, [%4];"
        : "=r"(r0), "=r"(r1), "=r"(r2), "=r"(r3) : "r"(addr));
}

// ===========================================================================
// Init: FIRE log tables
// ===========================================================================
__global__ void init_tables(const float* __restrict__ cp,
                            const float* __restrict__ lm) {
    const int i = blockIdx.x * blockDim.x + threadIdx.x;
    if (i >= TSEQ) return;
    const float c   = cp[0];
    const float thr = fabsf(lm[0] * 512.0f);
    g_utab[i] = logf(fabsf(c * (float)i) + 1.0f);
    g_invP[i] = 1.0f / (logf(fabsf(c * fmaxf((float)i, thr)) + 1.0f) + 1e-6f);
}

// ===========================================================================
// tf32 mma.sync GEMM (unchanged from R4)
// ===========================================================================
template <int MODE>
__global__ __launch_bounds__(256) void mma_gemm(const float* __restrict__ A,
                                                const float* __restrict__ Bm,
                                                const float* __restrict__ bias,
                                                float* __restrict__ out,
                                                int K, int N) {
    __shared__ float As[2][128][20];
    __shared__ float Bs[2][16][136];

    const int tid   = threadIdx.x;
    const int lane  = tid & 31;
    const int wid   = tid >> 5;
    const int warpM = wid & 3;
    const int warpN = wid >> 2;
    const int m0    = blockIdx.y * 128;
    const int n0    = blockIdx.x * 128;

    const int ar = tid >> 2;
    const int ak = (tid & 3) * 4;
    const float* Ag = A + (size_t)(m0 + ar) * K + ak;
    const int br = tid >> 4;
    const int bc = (tid & 15) * 4;
    const float* Bg = Bm + (size_t)br * N + n0 + bc;

    const uint32_t sA = smem_u32(As);
    const uint32_t sB = smem_u32(Bs);
    const uint32_t aOff0 = (uint32_t)(ar * 20 + ak) * 4;
    const uint32_t aOff1 = (uint32_t)((ar + 64) * 20 + ak) * 4;
    const uint32_t bOff0 = (uint32_t)(br * 136 + bc) * 4;
    const uint32_t bOff1 = (uint32_t)(br * 136 + bc + 64) * 4;
    const uint32_t ABUF = 128 * 20 * 4;
    const uint32_t BBUF = 16 * 136 * 4;

#define LOADTILE(buf, kc)                                                  \
    do {                                                                   \
        CP_ASYNC16(sA + (buf) * ABUF + aOff0, Ag + (kc));                  \
        CP_ASYNC16(sA + (buf) * ABUF + aOff1, Ag + (size_t)64 * K + (kc)); \
        CP_ASYNC16(sB + (buf) * BBUF + bOff0, Bg + (size_t)(kc) * N);      \
        CP_ASYNC16(sB + (buf) * BBUF + bOff1, Bg + (size_t)(kc) * N + 64); \
        CP_COMMIT();                                                       \
    } while (0)

    float acc[2][8][4];
#pragma unroll
    for (int mf = 0; mf < 2; mf++)
#pragma unroll
        for (int nf = 0; nf < 8; nf++)
#pragma unroll
            for (int i = 0; i < 4; i++) acc[mf][nf][i] = 0.0f;

    const int r  = lane >> 2;
    const int cq = lane & 3;
    const int nk = K >> 4;

    LOADTILE(0, 0);

#pragma unroll 1
    for (int it = 0; it < nk; it++) {
        const int buf = it & 1;
        if (it + 1 < nk) {
            LOADTILE((it + 1) & 1, (it + 1) * 16);
            CP_WAIT(1);
        } else {
            CP_WAIT(0);
        }
        __syncthreads();

#pragma unroll
        for (int ks = 0; ks < 2; ks++) {
            const int kb = ks * 8;
            uint32_t af[2][4];
#pragma unroll
            for (int mf = 0; mf < 2; mf++) {
                const int mrow = warpM * 32 + mf * 16 + r;
                af[mf][0] = f2tf32(As[buf][mrow][kb + cq]);
                af[mf][1] = f2tf32(As[buf][mrow + 8][kb + cq]);
                af[mf][2] = f2tf32(As[buf][mrow][kb + cq + 4]);
                af[mf][3] = f2tf32(As[buf][mrow + 8][kb + cq + 4]);
            }
#pragma unroll
            for (int nf = 0; nf < 8; nf++) {
                const int ncol = warpN * 64 + nf * 8 + r;
                uint32_t bf[2];
                bf[0] = f2tf32(Bs[buf][kb + cq][ncol]);
                bf[1] = f2tf32(Bs[buf][kb + cq + 4][ncol]);
                mma8(acc[0][nf], af[0], bf);
                mma8(acc[1][nf], af[1], bf);
            }
        }
        __syncthreads();
    }

#pragma unroll
    for (int mf = 0; mf < 2; mf++) {
#pragma unroll
        for (int nf = 0; nf < 8; nf++) {
            const int n = n0 + warpN * 64 + nf * 8 + 2 * cq;
            const float bx = bias[n], by = bias[n + 1];
#pragma unroll
            for (int half = 0; half < 2; half++) {
                const int m = m0 + warpM * 32 + mf * 16 + r + half * 8;
                float2 v = make_float2(acc[mf][nf][half * 2] + bx,
                                       acc[mf][nf][half * 2 + 1] + by);
                if (MODE == 0) {
                    const int which = n >> 10;
                    const int hh    = (n & 1023) >> 6;
                    const int d     = n & 63;
                    const int bb    = m >> 11;
                    const int t     = m & 2047;
                    *(float2*)&g_qkv[which * (BSZ * NH * TSEQ * HD) +
                                     ((bb * NH + hh) * TSEQ + t) * HD + d] = v;
                } else {
                    *(float2*)&out[(size_t)m * N + n] = v;
                }
            }
        }
    }
#undef LOADTILE
}

// ===========================================================================
// FA2-style flash attention, tf32 mma.sync, fused FIRE bias.
// 256 threads / 8 warps; warp owns 16 q-rows; 32-key tiles.
// K smem [32][68] row-major; V smem transposed [64][36]. All tensor operands
// rna-rounded to tf32 before use (unbiased; raw-bit truncation is biased).
// ===========================================================================
__device__ __forceinline__ float fire_mlp(float nd, const float* sw1,
                                          const float* sb1, const float* sw2,
                                          float b2h) {
    float acc = b2h;
#pragma unroll
    for (int w = 0; w < MLPW; w++)
        acc = fmaf(fmaxf(fmaf(nd, sw1[w], sb1[w]), 0.0f), sw2[w], acc);
    return acc;
}

__global__ __launch_bounds__(256) void attn_mma(
        const float* __restrict__ w1, const float* __restrict__ b1,
        const float* __restrict__ w2, const float* __restrict__ b2) {
    __shared__ __align__(16) float Ks[2][32][68];
    __shared__ __align__(16) float Vt[2][64][36];
    __shared__ float sw1[MLPW], sb1[MLPW], sw2[MLPW];
    __shared__ float s_alpha;
    __shared__ int   s_lin;

    const int tid  = threadIdx.x;
    const int lane = tid & 31;
    const int warp = tid >> 5;
    const int h    = blockIdx.y;
    const int b    = blockIdx.z;
    const int q0   = (gridDim.x - 1 - blockIdx.x) * 128;  // heavy blocks first
    const int tw   = q0 + warp * 16;
    const int r    = lane >> 2;
    const int cq   = lane & 3;
    const int t0   = tw + r;
    const int t1   = t0 + 8;

    if (tid < MLPW) {
        sw1[tid] = w1[tid];
        sb1[tid] = b1[tid];
        sw2[tid] = w2[tid * NH + h];
    }
    __syncthreads();
    if (tid == 0) {
        bool  lin = true;
        float a   = 0.0f;
#pragma unroll
        for (int w = 0; w < MLPW; w++) {
            lin = lin && (sb1[w] == 0.0f);
            a   = fmaf(fmaxf(sw1[w], 0.0f), sw2[w], a);
        }
        s_alpha = a;
        s_lin   = lin ? 1 : 0;
    }

    const float b2h   = b2[h];
    const float invP0 = g_invP[t0];
    const float invP1 = g_invP[t1];

    const float* Qg = g_qkv + (size_t)(b * NH + h) * TSEQ * HD;
    const float* Kg = Qg + (size_t)BSZ * NH * TSEQ * HD;
    const float* Vg = Kg + (size_t)BSZ * NH * TSEQ * HD;

    // Q a-frags (pre-scaled by 1/sqrt(hd), rna tf32)
    uint32_t qa[8][4];
#pragma unroll
    for (int kf = 0; kf < 8; kf++) {
        qa[kf][0] = f2tf32(Qg[(size_t)t0 * HD + kf * 8 + cq] * 0.125f);
        qa[kf][1] = f2tf32(Qg[(size_t)t1 * HD + kf * 8 + cq] * 0.125f);
        qa[kf][2] = f2tf32(Qg[(size_t)t0 * HD + kf * 8 + cq + 4] * 0.125f);
        qa[kf][3] = f2tf32(Qg[(size_t)t1 * HD + kf * 8 + cq + 4] * 0.125f);
    }

    float o[8][4];
#pragma unroll
    for (int nd = 0; nd < 8; nd++)
#pragma unroll
        for (int i = 0; i < 4; i++) o[nd][i] = 0.0f;
    float m0 = -1e30f, m1 = -1e30f, l0 = 0.0f, l1 = 0.0f;

    // Cooperative loaders: K rows via float4, V transposed via scalars
    const int krow = tid >> 3;       // 0..31 key row
    const int kc   = tid & 7;        // float4 slot / d-phase
    float4 kreg0, kreg1;
    float  vreg[8];

    // Prologue: tile 0 into buf 0
    {
        const float4* kp = (const float4*)&Kg[(size_t)krow * HD];
        kreg0 = kp[kc];
        kreg1 = kp[kc + 8];
#pragma unroll
        for (int i = 0; i < 8; i++)
            vreg[i] = Vg[(size_t)krow * HD + kc + 8 * i];
        float4 c0 = make_float4(rnaf(kreg0.x), rnaf(kreg0.y), rnaf(kreg0.z), rnaf(kreg0.w));
        float4 c1 = make_float4(rnaf(kreg1.x), rnaf(kreg1.y), rnaf(kreg1.z), rnaf(kreg1.w));
        *(float4*)&Ks[0][krow][kc * 4]      = c0;
        *(float4*)&Ks[0][krow][kc * 4 + 32] = c1;
#pragma unroll
        for (int i = 0; i < 8; i++) Vt[0][kc + 8 * i][krow] = rnaf(vreg[i]);
    }
    __syncthreads();

    const int   lin   = s_lin;
    const float alpha = s_alpha;
    const float ai0   = alpha * invP0;
    const float ai1   = alpha * invP1;

    const int nt = (q0 + 128) >> 5;
#pragma unroll 1
    for (int it = 0; it < nt; it++) {
        const int  buf = it & 1;
        const int  s0  = it * 32;
        const bool nxt = (it + 1) < nt;

        if (nxt) {  // prefetch next tile into regs (overlaps compute)
            const float4* kp = (const float4*)&Kg[(size_t)(s0 + 32 + krow) * HD];
            kreg0 = kp[kc];
            kreg1 = kp[kc + 8];
#pragma unroll
            for (int i = 0; i < 8; i++)
                vreg[i] = Vg[(size_t)(s0 + 32 + krow) * HD + kc + 8 * i];
        }

        if (s0 <= tw + 15) {  // warp-uniform causal skip
            const bool     msk = (s0 + 31) > tw;
            const uint32_t kb  = smem_u32(&Ks[buf][0][0]);
            const uint32_t vb  = smem_u32(&Vt[buf][0][0]);

            // ---- QK^T ----
            float s[4][4];
#pragma unroll
            for (int nf = 0; nf < 4; nf++) {
                s[nf][0] = s[nf][1] = s[nf][2] = s[nf][3] = 0.0f;
#pragma unroll
                for (int kfp = 0; kfp < 4; kfp++) {
                    uint32_t bb[4];
                    const uint32_t addr = kb +
                        4u * ((uint32_t)(8 * nf + (lane & 7)) * 68u +
                              16u * kfp + 4u * (lane >> 3));
                    ldm_x4(bb[0], bb[1], bb[2], bb[3], addr);
                    mma8(s[nf], qa[2 * kfp], bb);
                    mma8(s[nf], qa[2 * kfp + 1], bb + 2);
                }
            }

            // ---- bias + mask + tile max ----
            float mt0 = -1e30f, mt1 = -1e30f;
#pragma unroll
            for (int nf = 0; nf < 4; nf++) {
                const int k0    = s0 + nf * 8 + 2 * cq;
                const int rel00 = t0 - k0;
                const int rel01 = rel00 - 1;
                const int rel10 = rel00 + 8;
                const int rel11 = rel00 + 7;
                const float u00 = __ldg(&g_utab[rel00 < 0 ? 0 : rel00]);
                const float u01 = __ldg(&g_utab[rel01 < 0 ? 0 : rel01]);
                const float u10 = __ldg(&g_utab[rel10 < 0 ? 0 : rel10]);
                const float u11 = __ldg(&g_utab[rel11 < 0 ? 0 : rel11]);
                float b00, b01, b10, b11;
                if (lin) {
                    b00 = fmaf(ai0, u00, b2h);
                    b01 = fmaf(ai0, u01, b2h);
                    b10 = fmaf(ai1, u10, b2h);
                    b11 = fmaf(ai1, u11, b2h);
                } else {
                    b00 = fire_mlp(u00 * invP0, sw1, sb1, sw2, b2h);
                    b01 = fire_mlp(u01 * invP0, sw1, sb1, sw2, b2h);
                    b10 = fire_mlp(u10 * invP1, sw1, sb1, sw2, b2h);
                    b11 = fire_mlp(u11 * invP1, sw1, sb1, sw2, b2h);
                }
                s[nf][0] += b00;
                s[nf][1] += b01;
                s[nf][2] += b10;
                s[nf][3] += b11;
                if (msk) {
                    if (rel00 < 0) s[nf][0] = -1e30f;
                    if (rel01 < 0) s[nf][1] = -1e30f;
                    if (rel10 < 0) s[nf][2] = -1e30f;
                    if (rel11 < 0) s[nf][3] = -1e30f;
                }
                mt0 = fmaxf(mt0, fmaxf(s[nf][0], s[nf][1]));
                mt1 = fmaxf(mt1, fmaxf(s[nf][2], s[nf][3]));
            }
            mt0 = fmaxf(mt0, __shfl_xor_sync(0xffffffffu, mt0, 1));
            mt0 = fmaxf(mt0, __shfl_xor_sync(0xffffffffu, mt0, 2));
            mt1 = fmaxf(mt1, __shfl_xor_sync(0xffffffffu, mt1, 1));
            mt1 = fmaxf(mt1, __shfl_xor_sync(0xffffffffu, mt1, 2));

            const float mn0 = fmaxf(m0, mt0);
            const float mn1 = fmaxf(m1, mt1);
            const float f0  = __expf(m0 - mn0);
            const float f1  = __expf(m1 - mn1);
            m0 = mn0; m1 = mn1;
            l0 *= f0;  l1 *= f1;
#pragma unroll
            for (int nd = 0; nd < 8; nd++) {
                o[nd][0] *= f0; o[nd][1] *= f0;
                o[nd][2] *= f1; o[nd][3] *= f1;
            }
#pragma unroll
            for (int nf = 0; nf < 4; nf++) {
                s[nf][0] = __expf(s[nf][0] - m0);
                s[nf][1] = __expf(s[nf][1] - m0);
                s[nf][2] = __expf(s[nf][2] - m1);
                s[nf][3] = __expf(s[nf][3] - m1);
                l0 += s[nf][0] + s[nf][1];
                l1 += s[nf][2] + s[nf][3];
            }

            // ---- PV: shuffle P (C-layout -> A-layout), ldmatrix V ----
            const int src1 = (lane & 28) | (cq >> 1);
            const int src2 = src1 + 2;
#pragma unroll
            for (int kf2 = 0; kf2 < 4; kf2++) {
                const float x0 = __shfl_sync(0xffffffffu, s[kf2][0], src1);
                const float x1 = __shfl_sync(0xffffffffu, s[kf2][1], src1);
                const float y0 = __shfl_sync(0xffffffffu, s[kf2][0], src2);
                const float y1 = __shfl_sync(0xffffffffu, s[kf2][1], src2);
                const float x2 = __shfl_sync(0xffffffffu, s[kf2][2], src1);
                const float x3 = __shfl_sync(0xffffffffu, s[kf2][3], src1);
                const float y2 = __shfl_sync(0xffffffffu, s[kf2][2], src2);
                const float y3 = __shfl_sync(0xffffffffu, s[kf2][3], src2);
                uint32_t pa[4];
                pa[0] = f2tf32((cq & 1) ? x1 : x0);
                pa[1] = f2tf32((cq & 1) ? x3 : x2);
                pa[2] = f2tf32((cq & 1) ? y1 : y0);
                pa[3] = f2tf32((cq & 1) ? y3 : y2);
#pragma unroll
                for (int g = 0; g < 4; g++) {
                    uint32_t bv[4];
                    const uint32_t addr = vb +
                        4u * ((uint32_t)(8 * (2 * g + (lane >> 4)) + (lane & 7)) * 36u +
                              8u * kf2 + 4u * ((lane >> 3) & 1));
                    ldm_x4(bv[0], bv[1], bv[2], bv[3], addr);
                    mma8(o[2 * g], pa, bv);
                    mma8(o[2 * g + 1], pa, bv + 2);
                }
            }
        }

        if (nxt) {  // stage prefetched tile into other buffer
            const int nb = buf ^ 1;
            float4 c0 = make_float4(rnaf(kreg0.x), rnaf(kreg0.y), rnaf(kreg0.z), rnaf(kreg0.w));
            float4 c1 = make_float4(rnaf(kreg1.x), rnaf(kreg1.y), rnaf(kreg1.z), rnaf(kreg1.w));
            *(float4*)&Ks[nb][krow][kc * 4]      = c0;
            *(float4*)&Ks[nb][krow][kc * 4 + 32] = c1;
#pragma unroll
            for (int i = 0; i < 8; i++) Vt[nb][kc + 8 * i][krow] = rnaf(vreg[i]);
        }
        __syncthreads();
    }

    // ---- finalize: reduce l across quad, normalize, store ----
    l0 += __shfl_xor_sync(0xffffffffu, l0, 1);
    l0 += __shfl_xor_sync(0xffffffffu, l0, 2);
    l1 += __shfl_xor_sync(0xffffffffu, l1, 1);
    l1 += __shfl_xor_sync(0xffffffffu, l1, 2);
    const float inv0 = 1.0f / l0;
    const float inv1 = 1.0f / l1;
    float* y0p = &g_y[((size_t)(b * TSEQ) + t0) * CDIM + h * HD];
    float* y1p = &g_y[((size_t)(b * TSEQ) + t1) * CDIM + h * HD];
#pragma unroll
    for (int nd = 0; nd < 8; nd++) {
        const int d = nd * 8 + 2 * cq;
        *(float2*)&y0p[d] = make_float2(o[nd][0] * inv0, o[nd][1] * inv0);
        *(float2*)&y1p[d] = make_float2(o[nd][2] * inv1, o[nd][3] * inv1);
    }
}

// ===========================================================================
// Launch
// ===========================================================================
extern "C" void kernel_launch(void* const* d_in, const int* in_sizes, int n_in,
                              void* d_out, int out_size) {
    const float* x     = (const float*)d_in[0];
    const float* Wqkv  = (const float*)d_in[1];
    const float* bqkv  = (const float*)d_in[2];
    const float* Wproj = (const float*)d_in[3];
    const float* bproj = (const float*)d_in[4];
    const float* w1    = (const float*)d_in[5];
    const float* b1    = (const float*)d_in[6];
    const float* w2    = (const float*)d_in[7];
    const float* b2    = (const float*)d_in[8];
    const float* cpar  = (const float*)d_in[9];
    const float* lmul  = (const float*)d_in[10];
    float* out = (float*)d_out;

    init_tables<<<TSEQ / 256, 256>>>(cpar, lmul);

    // QKV: (4096 x 1024) @ (1024 x 3072) -> scatter into g_qkv
    mma_gemm<0><<<dim3(3 * CDIM / 128, BSZ * TSEQ / 128), 256>>>(
        x, Wqkv, bqkv, nullptr, CDIM, 3 * CDIM);

    // Flash attention (tensor cores) + fused FIRE bias
    attn_mma<<<dim3(TSEQ / 128, NH, BSZ), 256>>>(w1, b1, w2, b2);

    // Proj: (4096 x 1024) @ (1024 x 1024) -> out
    float* gy_ptr = nullptr;
    cudaGetSymbolAddress((void**)&gy_ptr, g_y);
    mma_gemm<1><<<dim3(CDIM / 128, BSZ * TSEQ / 128), 256>>>(
        gy_ptr, Wproj, bproj, out, CDIM, CDIM);
}